// round 6
// baseline (speedup 1.0000x reference)
#include <cuda_runtime.h>
#include <math.h>

// ---------------- geometry ----------------
#define W_    2048
#define HOUT  2046                 // VALID 3x3 output dim
#define NTOT  (W_ * W_)

// warp-strip decomposition: thread = 2 cols (float2), warp = 64 input cols,
// 62 owned output cols. Strip 32 ends exactly at col 2048 -> no col clipping.
#define COLS_OUT 62
#define R_OUT  20
#define STRIPS 33                  // 33*62 = 2046 exactly
#define BANDS  103                 // ceil(2046/20)
#define NWARPS (STRIPS * BANDS)    // 3399
#define WPB    8                   // warps per block (256 threads)
#define NBLOCKS ((NWARPS + WPB - 1) / WPB)  // 425

__device__ float g_bpart[3 * NBLOCKS];
__device__ unsigned int g_count;   // zero at module load; reset by last block

// raw per-row loads (issued early by the pipeline)
struct Raw { float2 E2, v2, s01, s23, s45; };

// per-row derived state: horizontal 3-sums and horizontal differences
struct RowState {
    float hE0, hE1;     // 3-sum of E centered at c0 / c0+1
    float hXX0, hXX1;   // 3-sum of sxx
    float hXY0, hXY1;   // 3-sum of sxy
    float dXY0, dXY1;   // sxy(j-1) - sxy(j+1) for j = c0-1 / c0
    float dYY0, dYY1;   // syy(j-1) - syy(j+1)
};

__device__ __forceinline__ float warp_sum(float x) {
#pragma unroll
    for (int o = 16; o > 0; o >>= 1) x += __shfl_down_sync(0xffffffffu, x, o);
    return x;
}

__device__ __forceinline__ Raw load_row(
    const float* __restrict__ pE, const float* __restrict__ pv,
    const float* __restrict__ ps, int base)
{
    Raw R;
    R.E2  = *reinterpret_cast<const float2*>(pE + base);
    R.v2  = *reinterpret_cast<const float2*>(pv + base);
    R.s01 = *reinterpret_cast<const float2*>(ps + 3 * base);
    R.s23 = *reinterpret_cast<const float2*>(ps + 3 * base + 2);
    R.s45 = *reinterpret_cast<const float2*>(ps + 3 * base + 4);
    return R;
}

__device__ __forceinline__ void compute_row(
    const Raw& R, RowState& o, bool ownrow, bool ownc0, bool ownc1, float& accE)
{
    const float E0 = R.E2.x,  E1 = R.E2.y;
    const float v0 = R.v2.x,  v1 = R.v2.y;
    const float e00 = R.s01.x, e10 = R.s01.y, e20 = R.s23.x;  // col c0
    const float e01 = R.s23.y, e11 = R.s45.x, e21 = R.s45.y;  // col c0+1

    const float f0 = __fdividef(E0, 1.0f - v0 * v0);
    const float f1 = __fdividef(E1, 1.0f - v1 * v1);
    const float xx0 = (e00 + v0 * e10) * f0;
    const float xx1 = (e01 + v1 * e11) * f1;
    const float yy0 = (v0 * e00 + e10) * f0;
    const float yy1 = (v1 * e01 + e11) * f1;
    const float xy0 = e20 * (1.0f - v0) * 0.5f * f0;
    const float xy1 = e21 * (1.0f - v1) * 0.5f * f1;

    // 8 shuffles/row; lane-edge garbage only feeds excluded outputs p=0/p=63
    const float El = __shfl_up_sync  (0xffffffffu, E1,  1);
    const float Er = __shfl_down_sync(0xffffffffu, E0,  1);
    const float xl = __shfl_up_sync  (0xffffffffu, xx1, 1);
    const float xr = __shfl_down_sync(0xffffffffu, xx0, 1);
    const float yl = __shfl_up_sync  (0xffffffffu, xy1, 1);
    const float yr = __shfl_down_sync(0xffffffffu, xy0, 1);
    const float sl = __shfl_up_sync  (0xffffffffu, yy1, 1);
    const float sr = __shfl_down_sync(0xffffffffu, yy0, 1);

    o.hE0  = El + E0 + E1;   o.hE1  = E0 + E1 + Er;
    o.hXX0 = xl + xx0 + xx1; o.hXX1 = xx0 + xx1 + xr;
    o.hXY0 = yl + xy0 + xy1; o.hXY1 = xy0 + xy1 + yr;
    o.dXY0 = yl - xy1;       o.dXY1 = xy0 - yr;
    o.dYY0 = sl - yy1;       o.dYY1 = yy0 - sr;

    if (ownrow) {
        if (ownc0) accE += E0;
        if (ownc1) accE += E1;
    }
}

__global__ __launch_bounds__(256, 2)
void stress_loss_kernel(const float* __restrict__ pE,
                        const float* __restrict__ pv,
                        const float* __restrict__ ps,
                        float* __restrict__ out)
{
    const int wl   = threadIdx.x >> 5;
    const int w    = blockIdx.x * WPB + wl;
    const int lane = threadIdx.x & 31;
    const int tid  = threadIdx.x;
    float accx = 0.f, accy = 0.f, accE = 0.f;

    if (w < NWARPS) {
        const int strip = w / BANDS;
        const int band  = w - strip * BANDS;
        const int cb = strip * COLS_OUT;
        const int r0 = band * R_OUT;
        const int rows_out = min(R_OUT, HOUT - r0);
        const int c0 = cb + lane * 2;
        const int own_hi_c = (strip == STRIPS - 1) ? W_ : cb + COLS_OUT;
        const int own_hi_r = (band  == BANDS  - 1) ? W_ : r0 + R_OUT;
        const bool ownc0 = (c0     < own_hi_c);
        const bool ownc1 = (c0 + 1 < own_hi_c);
        const bool ok0 = (lane > 0);    // output p = 2*lane   valid iff >=1
        const bool ok1 = (lane < 31);   // output p = 2*lane+1 valid iff <63

        // ---- software pipeline: load row r+1 while computing row r ----
        RowState A, B, C;
        {
            const Raw R0 = load_row(pE, pv, ps, r0 * W_ + c0);
            const Raw R1 = load_row(pE, pv, ps, (r0 + 1) * W_ + c0);
            compute_row(R0, A, (r0     < own_hi_r), ownc0, ownc1, accE);
            compute_row(R1, B, (r0 + 1 < own_hi_r), ownc0, ownc1, accE);
        }
        Raw P = load_row(pE, pv, ps, (r0 + 2) * W_ + c0);

#pragma unroll 4
        for (int i = 0; i < rows_out; i++) {
            const int r = r0 + i + 2;
            // prefetch next row (clamped; clamp only wastes an L2-hot load)
            const int rn = (r + 1 < W_) ? (r + 1) : (W_ - 1);
            const Raw N = load_row(pE, pv, ps, rn * W_ + c0);

            compute_row(P, C, (r < own_hi_r), ownc0, ownc1, accE);

            if (ok0) {
                const float Ec = A.hE0 + B.hE0 + C.hE0;
                const float fx = C.hXX0 - A.hXX0 + (A.dXY0 + B.dXY0 + C.dXY0);
                const float fy = (A.dYY0 + B.dYY0 + C.dYY0) + C.hXY0 - A.hXY0;
                const float inv = __fdividef(1.0f, Ec);
                accx += fabsf(fx * inv);
                accy += fabsf(fy * inv);
            }
            if (ok1) {
                const float Ec = A.hE1 + B.hE1 + C.hE1;
                const float fx = C.hXX1 - A.hXX1 + (A.dXY1 + B.dXY1 + C.dXY1);
                const float fy = (A.dYY1 + B.dYY1 + C.dYY1) + C.hXY1 - A.hXY1;
                const float inv = __fdividef(1.0f, Ec);
                accx += fabsf(fx * inv);
                accy += fabsf(fy * inv);
            }
            A = B; B = C; P = N;
        }
    }

    // ---- block reduction ----
    accx = warp_sum(accx);
    accy = warp_sum(accy);
    accE = warp_sum(accE);

    __shared__ float red[3][WPB];
    __shared__ int isLast;
    if (lane == 0) {
        red[0][wl] = accx;
        red[1][wl] = accy;
        red[2][wl] = accE;
    }
    __syncthreads();
    if (tid == 0) {
        float ax = 0.f, ay = 0.f, ae = 0.f;
#pragma unroll
        for (int q = 0; q < WPB; q++) { ax += red[0][q]; ay += red[1][q]; ae += red[2][q]; }
        g_bpart[blockIdx.x]               = ax;
        g_bpart[NBLOCKS + blockIdx.x]     = ay;
        g_bpart[2 * NBLOCKS + blockIdx.x] = ae;
        __threadfence();
        const unsigned int old = atomicAdd(&g_count, 1u);
        isLast = (old == NBLOCKS - 1);
    }
    __syncthreads();

    // ---- last block finalizes (fixed-order sum -> deterministic) ----
    if (isLast) {
        volatile const float* vp = (volatile const float*)g_bpart;
        double ax = 0.0, ay = 0.0, ae = 0.0;
        for (int i = tid; i < NBLOCKS; i += 256) {
            ax += (double)vp[i];
            ay += (double)vp[NBLOCKS + i];
            ae += (double)vp[2 * NBLOCKS + i];
        }
        __shared__ double sax[256], say[256], sae[256];
        sax[tid] = ax; say[tid] = ay; sae[tid] = ae;
        __syncthreads();
        for (int s = 128; s > 0; s >>= 1) {
            if (tid < s) { sax[tid] += sax[tid + s]; say[tid] += say[tid + s]; sae[tid] += sae[tid + s]; }
            __syncthreads();
        }
        if (tid == 0) {
            const double M = (double)HOUT * (double)HOUT;
            out[0] = (float)(sax[0] / M + say[0] / M
                             + fabs(sae[0] / (double)NTOT - 1.0) / 100.0);
            g_count = 0;   // reset for next graph replay
        }
    }
}

extern "C" void kernel_launch(void* const* d_in, const int* in_sizes, int n_in,
                              void* d_out, int out_size)
{
    const float* pred_E = (const float*)d_in[0];
    const float* pred_v = (const float*)d_in[1];
    const float* strain = (const float*)d_in[2];
    float* out = (float*)d_out;

    stress_loss_kernel<<<NBLOCKS, 256>>>(pred_E, pred_v, strain, out);
}

// round 7
// speedup vs baseline: 1.0960x; 1.0960x over previous
#include <cuda_runtime.h>
#include <math.h>

// ---------------- geometry ----------------
#define W_    2048
#define HOUT  2046                 // VALID 3x3 output dim
#define NTOT  (W_ * W_)

// warp-strip decomposition: thread = 2 cols (float2), warp = 64 input cols,
// 62 owned output cols. Each warp runs TWO independent 15-row streams
// (rows r0..r0+14 and r0+15..r0+29) to double memory-level parallelism.
#define COLS_OUT 62
#define R_OUT  30                  // total output rows per warp (15 + 15)
#define R_HALF 15
#define STRIPS 33                  // 33*62 = 2046 exactly
#define BANDS  69                  // ceil(2046/30)
#define NWARPS (STRIPS * BANDS)    // 2277
#define WPB    8                   // warps per block (256 threads)
#define NBLOCKS ((NWARPS + WPB - 1) / WPB)  // 285 -> single wave @ 2 blocks/SM

__device__ float g_bpart[3 * NBLOCKS];
__device__ unsigned int g_count;   // zero at module load; reset by last block

struct Raw { float2 E2, v2, s01, s23, s45; };

// per-row derived state: horizontal 3-sums and horizontal differences
struct RowState {
    float hE0, hE1;     // 3-sum of E centered at c0 / c0+1
    float hXX0, hXX1;   // 3-sum of sxx
    float hXY0, hXY1;   // 3-sum of sxy
    float dXY0, dXY1;   // sxy(j-1) - sxy(j+1)
    float dYY0, dYY1;   // syy(j-1) - syy(j+1)
};

__device__ __forceinline__ float warp_sum(float x) {
#pragma unroll
    for (int o = 16; o > 0; o >>= 1) x += __shfl_down_sync(0xffffffffu, x, o);
    return x;
}

__device__ __forceinline__ Raw load_row(
    const float* __restrict__ pE, const float* __restrict__ pv,
    const float* __restrict__ ps, int base)
{
    Raw R;
    R.E2  = *reinterpret_cast<const float2*>(pE + base);
    R.v2  = *reinterpret_cast<const float2*>(pv + base);
    R.s01 = *reinterpret_cast<const float2*>(ps + 3 * base);
    R.s23 = *reinterpret_cast<const float2*>(ps + 3 * base + 2);
    R.s45 = *reinterpret_cast<const float2*>(ps + 3 * base + 4);
    return R;
}

__device__ __forceinline__ void compute_row(
    const Raw& R, RowState& o, bool ownrow, bool ownc0, bool ownc1, float& accE)
{
    const float E0 = R.E2.x,  E1 = R.E2.y;
    const float v0 = R.v2.x,  v1 = R.v2.y;
    const float e00 = R.s01.x, e10 = R.s01.y, e20 = R.s23.x;  // col c0
    const float e01 = R.s23.y, e11 = R.s45.x, e21 = R.s45.y;  // col c0+1

    const float f0 = __fdividef(E0, 1.0f - v0 * v0);
    const float f1 = __fdividef(E1, 1.0f - v1 * v1);
    const float xx0 = (e00 + v0 * e10) * f0;
    const float xx1 = (e01 + v1 * e11) * f1;
    const float yy0 = (v0 * e00 + e10) * f0;
    const float yy1 = (v1 * e01 + e11) * f1;
    const float xy0 = e20 * (1.0f - v0) * 0.5f * f0;
    const float xy1 = e21 * (1.0f - v1) * 0.5f * f1;

    // 8 shuffles/row; lane-edge garbage only feeds excluded outputs p=0/p=63
    const float El = __shfl_up_sync  (0xffffffffu, E1,  1);
    const float Er = __shfl_down_sync(0xffffffffu, E0,  1);
    const float xl = __shfl_up_sync  (0xffffffffu, xx1, 1);
    const float xr = __shfl_down_sync(0xffffffffu, xx0, 1);
    const float yl = __shfl_up_sync  (0xffffffffu, xy1, 1);
    const float yr = __shfl_down_sync(0xffffffffu, xy0, 1);
    const float sl = __shfl_up_sync  (0xffffffffu, yy1, 1);
    const float sr = __shfl_down_sync(0xffffffffu, yy0, 1);

    o.hE0  = El + E0 + E1;   o.hE1  = E0 + E1 + Er;
    o.hXX0 = xl + xx0 + xx1; o.hXX1 = xx0 + xx1 + xr;
    o.hXY0 = yl + xy0 + xy1; o.hXY1 = xy0 + xy1 + yr;
    o.dXY0 = yl - xy1;       o.dXY1 = xy0 - yr;
    o.dYY0 = sl - yy1;       o.dYY1 = yy0 - sr;

    if (ownrow) {
        if (ownc0) accE += E0;
        if (ownc1) accE += E1;
    }
}

__device__ __forceinline__ void stencil(
    const RowState& A, const RowState& B, const RowState& C,
    bool ok0, bool ok1, float& accx, float& accy)
{
    if (ok0) {
        const float Ec = A.hE0 + B.hE0 + C.hE0;
        const float fx = C.hXX0 - A.hXX0 + (A.dXY0 + B.dXY0 + C.dXY0);
        const float fy = (A.dYY0 + B.dYY0 + C.dYY0) + C.hXY0 - A.hXY0;
        const float inv = __fdividef(1.0f, Ec);
        accx += fabsf(fx * inv);
        accy += fabsf(fy * inv);
    }
    if (ok1) {
        const float Ec = A.hE1 + B.hE1 + C.hE1;
        const float fx = C.hXX1 - A.hXX1 + (A.dXY1 + B.dXY1 + C.dXY1);
        const float fy = (A.dYY1 + B.dYY1 + C.dYY1) + C.hXY1 - A.hXY1;
        const float inv = __fdividef(1.0f, Ec);
        accx += fabsf(fx * inv);
        accy += fabsf(fy * inv);
    }
}

__global__ __launch_bounds__(256, 2)
void stress_loss_kernel(const float* __restrict__ pE,
                        const float* __restrict__ pv,
                        const float* __restrict__ ps,
                        float* __restrict__ out)
{
    const int wl   = threadIdx.x >> 5;
    const int w    = blockIdx.x * WPB + wl;
    const int lane = threadIdx.x & 31;
    const int tid  = threadIdx.x;
    float accx = 0.f, accy = 0.f, accE = 0.f;

    if (w < NWARPS) {
        const int strip = w / BANDS;
        const int band  = w - strip * BANDS;
        const int cb = strip * COLS_OUT;
        const int r0 = band * R_OUT;                 // stream-0 first output row
        const int r1 = r0 + R_HALF;                  // stream-1 first output row
        const int rows_total = min(R_OUT, HOUT - r0);
        const int rows0 = min(R_HALF, rows_total);   // 15 (or 6 on last band)
        const int rows1 = rows_total - rows0;        // 15 (or 0 on last band)
        const int c0 = cb + lane * 2;
        const int own_hi_c = (strip == STRIPS - 1) ? W_ : cb + COLS_OUT;
        const int own_hi_r = (band  == BANDS  - 1) ? W_ : r0 + R_OUT;
        const int own_hi0  = min(r0 + R_HALF, own_hi_r);  // stream-0 owns [r0, own_hi0)
        const bool ownc0 = (c0     < own_hi_c);
        const bool ownc1 = (c0 + 1 < own_hi_c);
        const bool ok0 = (lane > 0);
        const bool ok1 = (lane < 31);

        RowState A0, B0, C0, A1, B1, C1;
        // ---- warmup: interleave both streams' loads before any compute ----
        {
            const Raw Ra = load_row(pE, pv, ps, r0 * W_ + c0);
            const Raw Rb = load_row(pE, pv, ps, min(r1, W_ - 1) * W_ + c0);
            const Raw Rc = load_row(pE, pv, ps, (r0 + 1) * W_ + c0);
            const Raw Rd = load_row(pE, pv, ps, min(r1 + 1, W_ - 1) * W_ + c0);
            compute_row(Ra, A0, (r0     < own_hi0),  ownc0, ownc1, accE);
            compute_row(Rb, A1, (r1     < own_hi_r), ownc0, ownc1, accE);
            compute_row(Rc, B0, (r0 + 1 < own_hi0),  ownc0, ownc1, accE);
            compute_row(Rd, B1, (r1 + 1 < own_hi_r), ownc0, ownc1, accE);
        }

#pragma unroll 3
        for (int i = 0; i < rows0; i++) {
            const int ra = r0 + i + 2;                       // always < W_
            const int rb = r1 + i + 2;                       // may exceed on last band
            const Raw Ra = load_row(pE, pv, ps, ra * W_ + c0);
            const Raw Rb = load_row(pE, pv, ps, min(rb, W_ - 1) * W_ + c0);

            compute_row(Ra, C0, (ra < own_hi0),  ownc0, ownc1, accE);
            compute_row(Rb, C1, (rb < own_hi_r), ownc0, ownc1, accE);

            stencil(A0, B0, C0, ok0, ok1, accx, accy);
            if (i < rows1) stencil(A1, B1, C1, ok0, ok1, accx, accy);

            A0 = B0; B0 = C0;
            A1 = B1; B1 = C1;
        }
    }

    // ---- block reduction ----
    accx = warp_sum(accx);
    accy = warp_sum(accy);
    accE = warp_sum(accE);

    __shared__ float red[3][WPB];
    __shared__ int isLast;
    if (lane == 0) {
        red[0][wl] = accx;
        red[1][wl] = accy;
        red[2][wl] = accE;
    }
    __syncthreads();
    if (tid == 0) {
        float ax = 0.f, ay = 0.f, ae = 0.f;
#pragma unroll
        for (int q = 0; q < WPB; q++) { ax += red[0][q]; ay += red[1][q]; ae += red[2][q]; }
        g_bpart[blockIdx.x]               = ax;
        g_bpart[NBLOCKS + blockIdx.x]     = ay;
        g_bpart[2 * NBLOCKS + blockIdx.x] = ae;
        __threadfence();
        const unsigned int old = atomicAdd(&g_count, 1u);
        isLast = (old == NBLOCKS - 1);
    }
    __syncthreads();

    // ---- last block finalizes (fixed-order sum -> deterministic) ----
    if (isLast) {
        volatile const float* vp = (volatile const float*)g_bpart;
        double ax = 0.0, ay = 0.0, ae = 0.0;
        for (int i = tid; i < NBLOCKS; i += 256) {
            ax += (double)vp[i];
            ay += (double)vp[NBLOCKS + i];
            ae += (double)vp[2 * NBLOCKS + i];
        }
        __shared__ double sax[256], say[256], sae[256];
        sax[tid] = ax; say[tid] = ay; sae[tid] = ae;
        __syncthreads();
        for (int s = 128; s > 0; s >>= 1) {
            if (tid < s) { sax[tid] += sax[tid + s]; say[tid] += say[tid + s]; sae[tid] += sae[tid + s]; }
            __syncthreads();
        }
        if (tid == 0) {
            const double M = (double)HOUT * (double)HOUT;
            out[0] = (float)(sax[0] / M + say[0] / M
                             + fabs(sae[0] / (double)NTOT - 1.0) / 100.0);
            g_count = 0;   // reset for next graph replay
        }
    }
}

extern "C" void kernel_launch(void* const* d_in, const int* in_sizes, int n_in,
                              void* d_out, int out_size)
{
    const float* pred_E = (const float*)d_in[0];
    const float* pred_v = (const float*)d_in[1];
    const float* strain = (const float*)d_in[2];
    float* out = (float*)d_out;

    stress_loss_kernel<<<NBLOCKS, 256>>>(pred_E, pred_v, strain, out);
}